// round 4
// baseline (speedup 1.0000x reference)
#include <cuda_runtime.h>
#include <cuda_bf16.h>
#include <cstdint>

#define BATCH 256
#define CCH   256       // C
#define LSQ   512       // L
#define TWOC  512       // 2C
#define KEFF  768       // 3*C : [wh | wl | wh] x [xh | xh | xl]

// ---------------------------------------------------------------------------
// Device scratch
// ---------------------------------------------------------------------------
// A packed per m-tile: [8 tiles][64 rows][768], rows r<32 -> W1 ch mt*32+r,
// rows r>=32 -> W2 ch mt*32+(r-32)
__device__ __nv_bfloat16  g_A[8 * 64 * KEFF];                      // 768 KB
__device__ __nv_bfloat16  g_xh[(size_t)BATCH * LSQ * CCH];         // 67 MB  [b, l, c]
__device__ __nv_bfloat16  g_xl[(size_t)BATCH * LSQ * CCH];         // 67 MB  [b, l, c]

// ---------------------------------------------------------------------------
// helpers
// ---------------------------------------------------------------------------
__device__ __forceinline__ uint32_t s2u(const void* p) {
    uint32_t a;
    asm("{ .reg .u64 t; cvta.to.shared.u64 t, %1; cvt.u32.u64 %0, t; }" : "=r"(a) : "l"(p));
    return a;
}
__device__ __forceinline__ void cpasync16(uint32_t dst, const void* src) {
    asm volatile("cp.async.cg.shared.global [%0], [%1], 16;" :: "r"(dst), "l"(src) : "memory");
}
__device__ __forceinline__ void cp_commit() {
    asm volatile("cp.async.commit_group;" ::: "memory");
}
__device__ __forceinline__ void cp_wait1() {
    asm volatile("cp.async.wait_group 1;" ::: "memory");
}
__device__ __forceinline__ void cp_wait0() {
    asm volatile("cp.async.wait_group 0;" ::: "memory");
}
__device__ __forceinline__ void ldm_x4(uint32_t* r, uint32_t addr) {
    asm volatile("ldmatrix.sync.aligned.m8n8.x4.shared.b16 {%0,%1,%2,%3}, [%4];"
                 : "=r"(r[0]), "=r"(r[1]), "=r"(r[2]), "=r"(r[3]) : "r"(addr));
}
__device__ __forceinline__ void mma_bf16(float* c, const uint32_t* a, uint32_t b0, uint32_t b1) {
    asm volatile(
        "mma.sync.aligned.m16n8k16.row.col.f32.bf16.bf16.f32 "
        "{%0,%1,%2,%3}, {%4,%5,%6,%7}, {%8,%9}, {%0,%1,%2,%3};"
        : "+f"(c[0]), "+f"(c[1]), "+f"(c[2]), "+f"(c[3])
        : "r"(a[0]), "r"(a[1]), "r"(a[2]), "r"(a[3]), "r"(b0), "r"(b1));
}

// ---------------------------------------------------------------------------
// Kernel 1: pack A into paired-row tiles  [8][64][768]
// ---------------------------------------------------------------------------
__global__ void prep_kernel(const float* __restrict__ W) {
    int i = blockIdx.x * blockDim.x + threadIdx.x;
    if (i >= 8 * 64 * KEFF) return;
    int t = i / (64 * KEFF);
    int rem = i - t * (64 * KEFF);
    int r = rem / KEFF;
    int keff = rem - r * KEFF;
    int k = keff & 255;
    // W-row: r<32 -> W1 channel t*32+r (cols 0..255); r>=32 -> W2 channel (cols 256..511)
    int ch = t * 32 + (r & 31);
    float w = (r < 32) ? W[ch * TWOC + k] : W[ch * TWOC + CCH + k];
    __nv_bfloat16 wh = __float2bfloat16(w);
    __nv_bfloat16 out;
    if (keff >= 256 && keff < 512)
        out = __float2bfloat16(w - __bfloat162float(wh));   // wl
    else
        out = wh;
    g_A[i] = out;
}

// ---------------------------------------------------------------------------
// Kernel 2: transpose + split x[b,c,l] f32 -> xh[b,l,c], xl[b,l,c] bf16
//   block: 32 l x 128 c; 8B coalesced stores (4 bf16 per thread)
// ---------------------------------------------------------------------------
__global__ __launch_bounds__(256)
void conv_kernel(const float* __restrict__ x) {
    __shared__ float tile[128][33];
    int b  = blockIdx.z;
    int l0 = blockIdx.x * 32;
    int c0 = blockIdx.y * 128;
    int lane = threadIdx.x & 31, w = threadIdx.x >> 5;   // w 0..7

    const float* xb = x + ((size_t)b * CCH + c0) * LSQ + l0;
#pragma unroll
    for (int i = 0; i < 16; i++) {
        int c = w + i * 8;
        tile[c][lane] = xb[(size_t)c * LSQ + lane];
    }
    __syncthreads();

#pragma unroll
    for (int i = 0; i < 4; i++) {
        int l = w + i * 8;
        int c4 = lane * 4;
        float v0 = tile[c4 + 0][l], v1 = tile[c4 + 1][l];
        float v2 = tile[c4 + 2][l], v3 = tile[c4 + 3][l];
        __nv_bfloat16 h0 = __float2bfloat16(v0), h1 = __float2bfloat16(v1);
        __nv_bfloat16 h2 = __float2bfloat16(v2), h3 = __float2bfloat16(v3);
        __nv_bfloat162 hh01 = __nv_bfloat162(h0, h1), hh23 = __nv_bfloat162(h2, h3);
        __nv_bfloat162 ll01 = __nv_bfloat162(__float2bfloat16(v0 - __bfloat162float(h0)),
                                             __float2bfloat16(v1 - __bfloat162float(h1)));
        __nv_bfloat162 ll23 = __nv_bfloat162(__float2bfloat16(v2 - __bfloat162float(h2)),
                                             __float2bfloat16(v3 - __bfloat162float(h3)));
        size_t o = ((size_t)b * LSQ + l0 + l) * CCH + c0 + c4;
        *(__nv_bfloat162*)(g_xh + o)     = hh01;
        *(__nv_bfloat162*)(g_xh + o + 2) = hh23;
        *(__nv_bfloat162*)(g_xl + o)     = ll01;
        *(__nv_bfloat162*)(g_xl + o + 2) = ll23;
    }
}

// ---------------------------------------------------------------------------
// Kernel 3: fused GEMM + gather + bias + InstanceNorm + ReLU
//   CTA tile M=64 (32 ch pairs) x N=512 (all L), K=768, BK=32, 3-stage cp.async
//   256 threads, warp grid 2(m) x 4(n): warp tile 32x128
// ---------------------------------------------------------------------------
#define BK      32
#define STRIDE  80
#define A_SZ    (64 * STRIDE)            // 5120
#define B_SZ    (512 * STRIDE)           // 40960
#define STAGE_B (A_SZ + B_SZ)            // 46080
#define STAGES  3
#define GSMEM   (STAGES * STAGE_B)       // 138240
#define NKT     (KEFF / BK)              // 24
#define YSTR    516                      // f32 row stride for Y smem (bank-spread)

__global__ __launch_bounds__(256)
void gemm_kernel(const int* __restrict__ idx,
                 const float* __restrict__ bias,
                 float* __restrict__ out) {
    extern __shared__ char smem[];
    const uint32_t sb = s2u(smem);
    const int tid = threadIdx.x;
    const int wid = tid >> 5;
    const int lane = tid & 31;
    const int mt = blockIdx.x;           // 0..7
    const int b  = blockIdx.y;

    const int warp_m = wid & 1;          // 0..1 (32 rows each)
    const int warp_n = wid >> 1;         // 0..3 (128 cols each)

    const uint32_t a_lm = (uint32_t)(warp_m * 32 + (lane & 15)) * STRIDE + ((lane >> 4) * 16);
    const uint32_t b_lm = (uint32_t)(warp_n * 128 + (lane & 7) + ((lane >> 4) << 3)) * STRIDE
                        + (((lane >> 3) & 1) * 16);

    float acc[2][16][4];
#pragma unroll
    for (int i = 0; i < 2; i++)
#pragma unroll
        for (int j = 0; j < 16; j++)
#pragma unroll
            for (int k = 0; k < 4; k++) acc[i][j][k] = 0.f;

    auto load_tile = [&](int kt, int s) {
        const uint32_t base = sb + s * STAGE_B;
        {   // A: 64 rows x 4 chunks = 256 -> 1 per thread
            int row = tid >> 2, c16 = tid & 3;
            const void* src = g_A + (size_t)(mt * 64 + row) * KEFF + kt * BK + c16 * 8;
            cpasync16(base + row * STRIDE + c16 * 16, src);
        }
        const __nv_bfloat16* xs = (kt < 16) ? g_xh : g_xl;
        const int kb = (kt & 7) * BK;
#pragma unroll
        for (int i = 0; i < 8; i++) {     // B: 512 rows x 4 chunks = 2048 -> 8 per thread
            int t = tid + i * 256;
            int row = t >> 2, c16 = t & 3;
            const void* src = xs + ((size_t)b * LSQ + row) * CCH + kb + c16 * 8;
            cpasync16(base + A_SZ + row * STRIDE + c16 * 16, src);
        }
        cp_commit();
    };

    load_tile(0, 0);
    load_tile(1, 1);

    for (int kt = 0; kt < NKT; kt++) {
        const int s = kt % STAGES;
        cp_wait1();
        __syncthreads();
        if (kt + 2 < NKT) load_tile(kt + 2, (kt + 2) % STAGES);
        else cp_commit();

        const uint32_t abase = sb + s * STAGE_B + a_lm;
        const uint32_t bbase = sb + s * STAGE_B + A_SZ + b_lm;
#pragma unroll
        for (int k16 = 0; k16 < 2; k16++) {
            uint32_t af[2][4], bf[8][4];
#pragma unroll
            for (int mi = 0; mi < 2; mi++)
                ldm_x4(af[mi], abase + mi * 16 * STRIDE + k16 * 32);
#pragma unroll
            for (int bi = 0; bi < 8; bi++)
                ldm_x4(bf[bi], bbase + bi * 16 * STRIDE + k16 * 32);
#pragma unroll
            for (int mi = 0; mi < 2; mi++)
#pragma unroll
                for (int ni = 0; ni < 16; ni++)
                    mma_bf16(acc[mi][ni], af[mi],
                             bf[ni >> 1][(ni & 1) * 2], bf[ni >> 1][(ni & 1) * 2 + 1]);
        }
        __syncthreads();
    }

    // ---------------- fused epilogue ----------------
    cp_wait0();
    __syncthreads();

    float* Y1s = (float*)smem;                 // [32][YSTR]
    float* Y2s = Y1s 	+ 32 * YSTR;              // [32][YSTR]
    int*   idxs = (int*)(Y1s + 64 * YSTR);     // [512]

    // stage accumulators: warp_m==0 -> Y1 (W1 rows), warp_m==1 -> Y2 (W2 rows)
    float* Yw = (warp_m == 0) ? Y1s : Y2s;
    const int grp = lane >> 2, quad = lane & 3;
#pragma unroll
    for (int mi = 0; mi < 2; mi++) {
        int rr = mi * 16 + grp;
#pragma unroll
        for (int ni = 0; ni < 16; ni++) {
            int col = warp_n * 128 + ni * 8 + quad * 2;
            *(float2*)&Yw[(size_t)rr * YSTR + col] = make_float2(acc[mi][ni][0], acc[mi][ni][1]);
            *(float2*)&Yw[(size_t)(rr + 8) * YSTR + col] = make_float2(acc[mi][ni][2], acc[mi][ni][3]);
        }
    }
    // load idx row for this batch
    const int* id = idx + (size_t)b * LSQ;
    idxs[tid] = id[tid];
    idxs[tid + 256] = id[tid + 256];
    __syncthreads();

    // per-warp: 4 channels each
#pragma unroll
    for (int it = 0; it < 4; it++) {
        const int c = wid * 4 + it;                       // 0..31
        const float bv = __ldg(&bias[mt * 32 + c]);
        const float* y1 = Y1s + (size_t)c * YSTR;
        const float* y2 = Y2s + (size_t)c * YSTR;
        float v[16];
        float s = 0.f, s2 = 0.f;
#pragma unroll
        for (int i = 0; i < 16; i++) {
            int l = lane + i * 32;
            int j = idxs[l];
            float g2 = (j < LSQ) ? y2[j] : 0.f;
            float y = y1[l] + g2 + bv;
            v[i] = y;
            s += y; s2 += y * y;
        }
#pragma unroll
        for (int o = 16; o > 0; o >>= 1) {
            s  += __shfl_xor_sync(0xffffffffu, s,  o);
            s2 += __shfl_xor_sync(0xffffffffu, s2, o);
        }
        const float inv_l = 1.0f / (float)LSQ;
        float mu  = s * inv_l;
        float var = s2 * inv_l - mu * mu;
        float rstd = rsqrtf(var + 1e-5f);

        float* o = out + ((size_t)b * CCH + mt * 32 + c) * LSQ;
#pragma unroll
        for (int i = 0; i < 16; i++) {
            int l = lane + i * 32;
            o[l] = fmaxf((v[i] - mu) * rstd, 0.f);
        }
    }
}

// ---------------------------------------------------------------------------
// launch
// ---------------------------------------------------------------------------
extern "C" void kernel_launch(void* const* d_in, const int* in_sizes, int n_in,
                              void* d_out, int out_size) {
    const float* x    = (const float*)d_in[0];   // [B, C, L]
    const int*   idx  = (const int*)d_in[1];     // [B, L]
    const float* W    = (const float*)d_in[2];   // [C, 2C]
    const float* bias = (const float*)d_in[3];   // [C]
    float* out = (float*)d_out;                  // [B, C, L]

    cudaFuncSetAttribute(gemm_kernel, cudaFuncAttributeMaxDynamicSharedMemorySize, GSMEM);

    // 1) pack A
    prep_kernel<<<(8 * 64 * KEFF + 255) / 256, 256>>>(W);

    // 2) transpose + bf16 split: grid (L/32, C/128, B)
    dim3 cgrid(LSQ / 32, CCH / 128, BATCH);
    conv_kernel<<<cgrid, 256>>>(x);

    // 3) fused GEMM + norm: grid (8 m-tiles, B)
    dim3 ggrid(8, BATCH);
    gemm_kernel<<<ggrid, 256, GSMEM>>>(idx, bias, out);
}

// round 6
// speedup vs baseline: 1.8615x; 1.8615x over previous
#include <cuda_runtime.h>
#include <cuda_bf16.h>
#include <cstdint>

#define BATCH 256
#define CCH   256       // C
#define LSQ   512       // L
#define TWOC  512       // 2C
#define KEFF  768       // 3*C : [wh | wl | wh] x [xh | xh | xl]

// ---------------------------------------------------------------------------
// Device scratch
// ---------------------------------------------------------------------------
__device__ float          g_G[(size_t)BATCH * TWOC * LSQ];        // 268 MB
__device__ __nv_bfloat16  g_A[TWOC * KEFF];                        // 768 KB
__device__ __nv_bfloat16  g_xh[(size_t)BATCH * LSQ * CCH];         // 67 MB  [b, l, c]
__device__ __nv_bfloat16  g_xl[(size_t)BATCH * LSQ * CCH];         // 67 MB  [b, l, c]

// ---------------------------------------------------------------------------
// helpers
// ---------------------------------------------------------------------------
__device__ __forceinline__ uint32_t s2u(const void* p) {
    uint32_t a;
    asm("{ .reg .u64 t; cvta.to.shared.u64 t, %1; cvt.u32.u64 %0, t; }" : "=r"(a) : "l"(p));
    return a;
}
__device__ __forceinline__ void cpasync16(uint32_t dst, const void* src) {
    asm volatile("cp.async.cg.shared.global [%0], [%1], 16;" :: "r"(dst), "l"(src) : "memory");
}
__device__ __forceinline__ void cp_commit() {
    asm volatile("cp.async.commit_group;" ::: "memory");
}
__device__ __forceinline__ void cp_wait1() {
    asm volatile("cp.async.wait_group 1;" ::: "memory");
}
__device__ __forceinline__ void ldm_x4(uint32_t* r, uint32_t addr) {
    asm volatile("ldmatrix.sync.aligned.m8n8.x4.shared.b16 {%0,%1,%2,%3}, [%4];"
                 : "=r"(r[0]), "=r"(r[1]), "=r"(r[2]), "=r"(r[3]) : "r"(addr));
}
__device__ __forceinline__ void mma_bf16(float* c, const uint32_t* a, uint32_t b0, uint32_t b1) {
    asm volatile(
        "mma.sync.aligned.m16n8k16.row.col.f32.bf16.bf16.f32 "
        "{%0,%1,%2,%3}, {%4,%5,%6,%7}, {%8,%9}, {%0,%1,%2,%3};"
        : "+f"(c[0]), "+f"(c[1]), "+f"(c[2]), "+f"(c[3])
        : "r"(a[0]), "r"(a[1]), "r"(a[2]), "r"(a[3]), "r"(b0), "r"(b1));
}

// ---------------------------------------------------------------------------
// Kernel 1: build A = [wh | wl | wh]  (512 x 768 bf16), from W [C, 2C]
// ---------------------------------------------------------------------------
__global__ void prep_kernel(const float* __restrict__ W) {
    int i = blockIdx.x * blockDim.x + threadIdx.x;
    if (i >= TWOC * KEFF) return;
    int m = i / KEFF;
    int keff = i - m * KEFF;
    int k = keff & 255;
    float w = (m < CCH) ? W[m * TWOC + k] : W[(m - CCH) * TWOC + CCH + k];
    __nv_bfloat16 wh = __float2bfloat16(w);
    __nv_bfloat16 out;
    if (keff >= 256 && keff < 512)
        out = __float2bfloat16(w - __bfloat162float(wh));   // wl
    else
        out = wh;
    g_A[i] = out;
}

// ---------------------------------------------------------------------------
// Kernel 2: transpose + split x[b,c,l] f32 -> xh[b,l,c], xl[b,l,c] bf16
//   block: 32 l x 128 c; 8B coalesced stores
// ---------------------------------------------------------------------------
__global__ __launch_bounds__(256)
void conv_kernel(const float* __restrict__ x) {
    __shared__ float tile[128][33];
    int b  = blockIdx.z;
    int l0 = blockIdx.x * 32;
    int c0 = blockIdx.y * 128;
    int lane = threadIdx.x & 31, w = threadIdx.x >> 5;

    const float* xb = x + ((size_t)b * CCH + c0) * LSQ + l0;
#pragma unroll
    for (int i = 0; i < 16; i++) {
        int c = w + i * 8;
        tile[c][lane] = xb[(size_t)c * LSQ + lane];
    }
    __syncthreads();

#pragma unroll
    for (int i = 0; i < 4; i++) {
        int l = w + i * 8;
        int c4 = lane * 4;
        float v0 = tile[c4 + 0][l], v1 = tile[c4 + 1][l];
        float v2 = tile[c4 + 2][l], v3 = tile[c4 + 3][l];
        __nv_bfloat16 h0 = __float2bfloat16(v0), h1 = __float2bfloat16(v1);
        __nv_bfloat16 h2 = __float2bfloat16(v2), h3 = __float2bfloat16(v3);
        __nv_bfloat162 hh01 = __nv_bfloat162(h0, h1), hh23 = __nv_bfloat162(h2, h3);
        __nv_bfloat162 ll01 = __nv_bfloat162(__float2bfloat16(v0 - __bfloat162float(h0)),
                                             __float2bfloat16(v1 - __bfloat162float(h1)));
        __nv_bfloat162 ll23 = __nv_bfloat162(__float2bfloat16(v2 - __bfloat162float(h2)),
                                             __float2bfloat16(v3 - __bfloat162float(h3)));
        size_t o = ((size_t)b * LSQ + l0 + l) * CCH + c0 + c4;
        *(__nv_bfloat162*)(g_xh + o)     = hh01;
        *(__nv_bfloat162*)(g_xh + o + 2) = hh23;
        *(__nv_bfloat162*)(g_xl + o)     = ll01;
        *(__nv_bfloat162*)(g_xl + o + 2) = ll23;
    }
}

// ---------------------------------------------------------------------------
// Kernel 3: mma.sync bf16 GEMM  G[b] (512x512) = A (512x768) @ B[b]^T
//   CTA 128x128, BK=64, 3-stage cp.async, 256 threads, warp grid 2x4.
//   smem rows: 64 bf16 = 128B data, stride 144B (16r mod 128 -> conflict-free)
// ---------------------------------------------------------------------------
#define BK      64
#define STRIDE  144
#define T_SZ    (128 * STRIDE)           // 18432 per operand tile
#define STAGE_B (2 * T_SZ)               // 36864 (A then B)
#define STAGES  3
#define GSMEM   (STAGES * STAGE_B)       // 110592
#define NKT     (KEFF / BK)              // 12

__global__ __launch_bounds__(256, 2)
void gemm_kernel() {
    extern __shared__ char smem[];
    const uint32_t sb = s2u(smem);
    const int tid = threadIdx.x;
    const int wid = tid >> 5;
    const int l   = tid & 31;
    const int b   = blockIdx.z;
    const int m0  = blockIdx.y * 128;
    const int n0  = blockIdx.x * 128;

    const int warp_m = wid & 1;          // 64 rows each
    const int warp_n = wid >> 1;         // 32 cols each

    const uint32_t a_lm = (uint32_t)(warp_m * 64 + (l & 15)) * STRIDE + ((l >> 4) * 16);
    const uint32_t b_lm = (uint32_t)(warp_n * 32 + (l & 7) + ((l >> 4) << 3)) * STRIDE
                        + (((l >> 3) & 1) * 16);

    // global load: 1024 16B chunks per operand, 4 per thread each
    const int g_row = tid >> 3;          // 0..31 (+32,+64,+96)
    const int g_col = tid & 7;           // 16B chunk within 128B row

    float acc[4][4][4];
#pragma unroll
    for (int i = 0; i < 4; i++)
#pragma unroll
        for (int j = 0; j < 4; j++)
#pragma unroll
            for (int k = 0; k < 4; k++) acc[i][j][k] = 0.f;

    auto load_tile = [&](int kt, int s) {
        const uint32_t base = sb + s * STAGE_B;
#pragma unroll
        for (int i = 0; i < 4; i++) {
            int row = g_row + i * 32;
            const void* src = g_A + (size_t)(m0 + row) * KEFF + kt * BK + g_col * 8;
            cpasync16(base + row * STRIDE + g_col * 16, src);
        }
        const __nv_bfloat16* xs = (kt < 8) ? g_xh : g_xl;
        const int kb = (kt & 3) * BK;
#pragma unroll
        for (int i = 0; i < 4; i++) {
            int row = g_row + i * 32;
            const void* src = xs + ((size_t)b * LSQ + n0 + row) * CCH + kb + g_col * 8;
            cpasync16(base + T_SZ + row * STRIDE + g_col * 16, src);
        }
        cp_commit();
    };

    load_tile(0, 0);
    load_tile(1, 1);

    for (int kt = 0; kt < NKT; kt++) {
        const int s = kt % STAGES;
        cp_wait1();
        __syncthreads();
        if (kt + 2 < NKT) load_tile(kt + 2, (kt + 2) % STAGES);
        else cp_commit();

        const uint32_t abase = sb + s * STAGE_B + a_lm;
        const uint32_t bbase = sb + s * STAGE_B + T_SZ + b_lm;
#pragma unroll
        for (int k16 = 0; k16 < 4; k16++) {
            uint32_t af[4][4], bf[2][4];
#pragma unroll
            for (int mi = 0; mi < 4; mi++)
                ldm_x4(af[mi], abase + mi * 16 * STRIDE + k16 * 32);
#pragma unroll
            for (int bi = 0; bi < 2; bi++)
                ldm_x4(bf[bi], bbase + bi * 16 * STRIDE + k16 * 32);
#pragma unroll
            for (int mi = 0; mi < 4; mi++)
#pragma unroll
                for (int ni = 0; ni < 4; ni++)
                    mma_bf16(acc[mi][ni], af[mi],
                             bf[ni >> 1][(ni & 1) * 2], bf[ni >> 1][(ni & 1) * 2 + 1]);
        }
        __syncthreads();
    }

    // epilogue: direct stores
    const int grp  = l >> 2;
    const int quad = l & 3;
#pragma unroll
    for (int mi = 0; mi < 4; mi++) {
        int r0 = m0 + warp_m * 64 + mi * 16 + grp;
#pragma unroll
        for (int ni = 0; ni < 4; ni++) {
            int col = n0 + warp_n * 32 + ni * 8 + quad * 2;
            float* p0 = g_G + ((size_t)b * TWOC + r0) * LSQ + col;
            float* p1 = p0 + 8 * LSQ;
            *(float2*)p0 = make_float2(acc[mi][ni][0], acc[mi][ni][1]);
            *(float2*)p1 = make_float2(acc[mi][ni][2], acc[mi][ni][3]);
        }
    }
}

// ---------------------------------------------------------------------------
// Kernel 4: fused combine + InstanceNorm + ReLU with smem gather
//   4 channels per block, 2 warps per channel; G2 rows staged in smem.
// ---------------------------------------------------------------------------
__global__ __launch_bounds__(256)
void norm_kernel(const int* __restrict__ idx,
                 const float* __restrict__ bias,
                 float* __restrict__ out) {
    __shared__ float sG2[4][LSQ];
    __shared__ int   sidx[LSQ];
    __shared__ float ps[4][2], ps2[4][2];

    const int c0 = blockIdx.x * 4;
    const int b  = blockIdx.y;
    const int tid = threadIdx.x;
    const int wid = tid >> 5, lane = tid & 31;

    // stage idx + 4 G2 rows (coalesced)
    const int* id = idx + (size_t)b * LSQ;
    sidx[tid] = id[tid];
    sidx[tid + 256] = id[tid + 256];
    const float* G2base = g_G + ((size_t)b * TWOC + CCH + c0) * LSQ;
#pragma unroll
    for (int i = 0; i < 8; i++) {
        int t = tid + i * 256;                // 0..2047
        ((float*)sG2)[t] = G2base[t];
    }
    __syncthreads();

    const int ch   = wid >> 1;                // 0..3
    const int half = wid & 1;                 // 0..1
    const float bv = __ldg(&bias[c0 + ch]);
    const float* G1 = g_G + ((size_t)b * TWOC + c0 + ch) * LSQ;

    float v[8];
    float s = 0.f, s2 = 0.f;
#pragma unroll
    for (int i = 0; i < 8; i++) {
        int l = half * 256 + lane + i * 32;
        int j = sidx[l];
        float g2 = (j < LSQ) ? sG2[ch][j] : 0.f;
        float y = G1[l] + g2 + bv;
        v[i] = y;
        s += y; s2 += y * y;
    }
#pragma unroll
    for (int o = 16; o > 0; o >>= 1) {
        s  += __shfl_xor_sync(0xffffffffu, s,  o);
        s2 += __shfl_xor_sync(0xffffffffu, s2, o);
    }
    if (lane == 0) { ps[ch][half] = s; ps2[ch][half] = s2; }
    __syncthreads();

    float st  = ps[ch][0]  + ps[ch][1];
    float st2 = ps2[ch][0] + ps2[ch][1];
    const float inv_l = 1.0f / (float)LSQ;
    float mu  = st * inv_l;
    float var = st2 * inv_l - mu * mu;
    float rstd = rsqrtf(var + 1e-5f);

    float* o = out + ((size_t)b * CCH + c0 + ch) * LSQ;
#pragma unroll
    for (int i = 0; i < 8; i++) {
        int l = half * 256 + lane + i * 32;
        o[l] = fmaxf((v[i] - mu) * rstd, 0.f);
    }
}

// ---------------------------------------------------------------------------
// launch
// ---------------------------------------------------------------------------
extern "C" void kernel_launch(void* const* d_in, const int* in_sizes, int n_in,
                              void* d_out, int out_size) {
    const float* x    = (const float*)d_in[0];   // [B, C, L]
    const int*   idx  = (const int*)d_in[1];     // [B, L]
    const float* W    = (const float*)d_in[2];   // [C, 2C]
    const float* bias = (const float*)d_in[3];   // [C]
    float* out = (float*)d_out;                  // [B, C, L]

    cudaFuncSetAttribute(gemm_kernel, cudaFuncAttributeMaxDynamicSharedMemorySize, GSMEM);

    prep_kernel<<<(TWOC * KEFF + 255) / 256, 256>>>(W);

    dim3 cgrid(LSQ / 32, CCH / 128, BATCH);
    conv_kernel<<<cgrid, 256>>>(x);

    dim3 ggrid(LSQ / 128, TWOC / 128, BATCH);
    gemm_kernel<<<ggrid, 256, GSMEM>>>();

    dim3 ngrid(CCH / 4, BATCH);
    norm_kernel<<<ngrid, 256>>>(idx, bias, out);
}

// round 7
// speedup vs baseline: 3.7406x; 2.0094x over previous
#include <cuda_runtime.h>
#include <cuda_fp16.h>
#include <cstdint>

#define BATCH 256
#define CCH   256       // C
#define LSQ   512       // L
#define TWOC  512       // 2C
#define KTOT  256       // single fp16 GEMM

// ---------------------------------------------------------------------------
// Device scratch
// ---------------------------------------------------------------------------
__device__ __half  g_G[(size_t)BATCH * TWOC * LSQ];    // 134 MB, fp16
__device__ __half  g_A[TWOC * KTOT];                    // 256 KB
__device__ __half  g_xh[(size_t)BATCH * LSQ * CCH];     // 67 MB  [b, l, c]

// ---------------------------------------------------------------------------
// helpers
// ---------------------------------------------------------------------------
__device__ __forceinline__ uint32_t s2u(const void* p) {
    uint32_t a;
    asm("{ .reg .u64 t; cvta.to.shared.u64 t, %1; cvt.u32.u64 %0, t; }" : "=r"(a) : "l"(p));
    return a;
}
__device__ __forceinline__ void cpasync16(uint32_t dst, const void* src) {
    asm volatile("cp.async.cg.shared.global [%0], [%1], 16;" :: "r"(dst), "l"(src) : "memory");
}
__device__ __forceinline__ void cp_commit() {
    asm volatile("cp.async.commit_group;" ::: "memory");
}
__device__ __forceinline__ void cp_wait1() {
    asm volatile("cp.async.wait_group 1;" ::: "memory");
}
__device__ __forceinline__ void ldm_x4(uint32_t* r, uint32_t addr) {
    asm volatile("ldmatrix.sync.aligned.m8n8.x4.shared.b16 {%0,%1,%2,%3}, [%4];"
                 : "=r"(r[0]), "=r"(r[1]), "=r"(r[2]), "=r"(r[3]) : "r"(addr));
}
__device__ __forceinline__ void mma_f16(float* c, const uint32_t* a, uint32_t b0, uint32_t b1) {
    asm volatile(
        "mma.sync.aligned.m16n8k16.row.col.f32.f16.f16.f32 "
        "{%0,%1,%2,%3}, {%4,%5,%6,%7}, {%8,%9}, {%0,%1,%2,%3};"
        : "+f"(c[0]), "+f"(c[1]), "+f"(c[2]), "+f"(c[3])
        : "r"(a[0]), "r"(a[1]), "r"(a[2]), "r"(a[3]), "r"(b0), "r"(b1));
}

// ---------------------------------------------------------------------------
// Kernel 1: A[m][k] = fp16(Wp), Wp[m][k] = m<C ? W[m][k] : W[m-C][C+k]
// ---------------------------------------------------------------------------
__global__ void prep_kernel(const float* __restrict__ W) {
    int i = blockIdx.x * blockDim.x + threadIdx.x;
    if (i >= TWOC * KTOT) return;
    int m = i >> 8;
    int k = i & 255;
    float w = (m < CCH) ? W[m * TWOC + k] : W[(m - CCH) * TWOC + CCH + k];
    g_A[i] = __float2half(w);
}

// ---------------------------------------------------------------------------
// Kernel 2: transpose + convert x[b,c,l] f32 -> xh[b,l,c] fp16
// ---------------------------------------------------------------------------
__global__ __launch_bounds__(256)
void conv_kernel(const float* __restrict__ x) {
    __shared__ float tile[128][33];
    int b  = blockIdx.z;
    int l0 = blockIdx.x * 32;
    int c0 = blockIdx.y * 128;
    int lane = threadIdx.x & 31, w = threadIdx.x >> 5;

    const float* xb = x + ((size_t)b * CCH + c0) * LSQ + l0;
#pragma unroll
    for (int i = 0; i < 16; i++) {
        int c = w + i * 8;
        tile[c][lane] = xb[(size_t)c * LSQ + lane];
    }
    __syncthreads();

#pragma unroll
    for (int i = 0; i < 4; i++) {
        int l = w + i * 8;
        int c4 = lane * 4;
        __half2 h01 = __floats2half2_rn(tile[c4 + 0][l], tile[c4 + 1][l]);
        __half2 h23 = __floats2half2_rn(tile[c4 + 2][l], tile[c4 + 3][l]);
        size_t o = ((size_t)b * LSQ + l0 + l) * CCH + c0 + c4;
        *(uint2*)(g_xh + o) = make_uint2(*(uint32_t*)&h01, *(uint32_t*)&h23);
    }
}

// ---------------------------------------------------------------------------
// Kernel 3: fp16 GEMM  G[b] (512x512 fp16) = A (512x256) @ B[b]^T (512x256)
//   CTA 128x128, BK=64, 3-stage cp.async, 256 threads, warp grid 2x4
// ---------------------------------------------------------------------------
#define BK      64
#define STRIDE  144
#define T_SZ    (128 * STRIDE)
#define STAGE_B (2 * T_SZ)
#define STAGES  3
#define GSMEM   (STAGES * STAGE_B)       // 110592
#define NKT     (KTOT / BK)              // 4

__global__ __launch_bounds__(256, 2)
void gemm_kernel() {
    extern __shared__ char smem[];
    const uint32_t sb = s2u(smem);
    const int tid = threadIdx.x;
    const int wid = tid >> 5;
    const int l   = tid & 31;
    const int b   = blockIdx.z;
    const int m0  = blockIdx.y * 128;
    const int n0  = blockIdx.x * 128;

    const int warp_m = wid & 1;
    const int warp_n = wid >> 1;

    const uint32_t a_lm = (uint32_t)(warp_m * 64 + (l & 15)) * STRIDE + ((l >> 4) * 16);
    const uint32_t b_lm = (uint32_t)(warp_n * 32 + (l & 7) + ((l >> 4) << 3)) * STRIDE
                        + (((l >> 3) & 1) * 16);

    const int g_row = tid >> 3;          // 0..31
    const int g_col = tid & 7;

    float acc[4][4][4];
#pragma unroll
    for (int i = 0; i < 4; i++)
#pragma unroll
        for (int j = 0; j < 4; j++)
#pragma unroll
            for (int k = 0; k < 4; k++) acc[i][j][k] = 0.f;

    auto load_tile = [&](int kt, int s) {
        const uint32_t base = sb + s * STAGE_B;
#pragma unroll
        for (int i = 0; i < 4; i++) {
            int row = g_row + i * 32;
            const void* src = g_A + (size_t)(m0 + row) * KTOT + kt * BK + g_col * 8;
            cpasync16(base + row * STRIDE + g_col * 16, src);
        }
#pragma unroll
        for (int i = 0; i < 4; i++) {
            int row = g_row + i * 32;
            const void* src = g_xh + ((size_t)b * LSQ + n0 + row) * CCH + kt * BK + g_col * 8;
            cpasync16(base + T_SZ + row * STRIDE + g_col * 16, src);
        }
        cp_commit();
    };

    load_tile(0, 0);
    load_tile(1, 1);

    for (int kt = 0; kt < NKT; kt++) {
        const int s = kt % STAGES;
        cp_wait1();
        __syncthreads();
        if (kt + 2 < NKT) load_tile(kt + 2, (kt + 2) % STAGES);
        else cp_commit();

        const uint32_t abase = sb + s * STAGE_B + a_lm;
        const uint32_t bbase = sb + s * STAGE_B + T_SZ + b_lm;
#pragma unroll
        for (int k16 = 0; k16 < 4; k16++) {
            uint32_t af[4][4], bf[2][4];
#pragma unroll
            for (int mi = 0; mi < 4; mi++)
                ldm_x4(af[mi], abase + mi * 16 * STRIDE + k16 * 32);
#pragma unroll
            for (int bi = 0; bi < 2; bi++)
                ldm_x4(bf[bi], bbase + bi * 16 * STRIDE + k16 * 32);
#pragma unroll
            for (int mi = 0; mi < 4; mi++)
#pragma unroll
                for (int ni = 0; ni < 4; ni++)
                    mma_f16(acc[mi][ni], af[mi],
                            bf[ni >> 1][(ni & 1) * 2], bf[ni >> 1][(ni & 1) * 2 + 1]);
        }
        __syncthreads();
    }

    // epilogue: convert to fp16, store
    const int grp  = l >> 2;
    const int quad = l & 3;
#pragma unroll
    for (int mi = 0; mi < 4; mi++) {
        int r0 = m0 + warp_m * 64 + mi * 16 + grp;
#pragma unroll
        for (int ni = 0; ni < 4; ni++) {
            int col = n0 + warp_n * 32 + ni * 8 + quad * 2;
            __half2 h0 = __floats2half2_rn(acc[mi][ni][0], acc[mi][ni][1]);
            __half2 h1 = __floats2half2_rn(acc[mi][ni][2], acc[mi][ni][3]);
            __half* p0 = g_G + ((size_t)b * TWOC + r0) * LSQ + col;
            *(__half2*)p0 = h0;
            *(__half2*)(p0 + 8 * LSQ) = h1;
        }
    }
}

// ---------------------------------------------------------------------------
// Kernel 4: combine + InstanceNorm + ReLU (bias cancels under InstanceNorm)
//   8 channels / block, 1 warp / channel; G2 rows staged in f32 smem.
// ---------------------------------------------------------------------------
__global__ __launch_bounds__(256)
void norm_kernel(const int* __restrict__ idx, float* __restrict__ out) {
    __shared__ float sG2[8][LSQ];
    __shared__ int   sidx[LSQ];

    const int c0 = blockIdx.x * 8;
    const int b  = blockIdx.y;
    const int tid = threadIdx.x;
    const int wid = tid >> 5, lane = tid & 31;

    const int* id = idx + (size_t)b * LSQ;
    sidx[tid] = id[tid];
    sidx[tid + 256] = id[tid + 256];

    const __half2* G2base = (const __half2*)(g_G + ((size_t)b * TWOC + CCH + c0) * LSQ);
#pragma unroll
    for (int i = 0; i < 8; i++) {
        int t = tid + i * 256;               // 0..2047 half2 idx
        float2 f = __half22float2(G2base[t]);
        ((float2*)sG2)[t] = f;
    }
    __syncthreads();

    const int ch = wid;
    const __half* G1 = g_G + ((size_t)b * TWOC + c0 + ch) * LSQ;

    float v[16];
    float s = 0.f, s2 = 0.f;
#pragma unroll
    for (int i = 0; i < 16; i++) {
        int l = lane + i * 32;
        int j = sidx[l];
        float g2 = (j < LSQ) ? sG2[ch][j] : 0.f;
        float y = __half2float(G1[l]) + g2;
        v[i] = y;
        s += y; s2 += y * y;
    }
#pragma unroll
    for (int o = 16; o > 0; o >>= 1) {
        s  += __shfl_xor_sync(0xffffffffu, s,  o);
        s2 += __shfl_xor_sync(0xffffffffu, s2, o);
    }
    const float inv_l = 1.0f / (float)LSQ;
    float mu  = s * inv_l;
    float var = s2 * inv_l - mu * mu;
    float rstd = rsqrtf(var + 1e-5f);

    float* o = out + ((size_t)b * CCH + c0 + ch) * LSQ;
#pragma unroll
    for (int i = 0; i < 16; i++) {
        int l = lane + i * 32;
        o[l] = fmaxf((v[i] - mu) * rstd, 0.f);
    }
}

// ---------------------------------------------------------------------------
// launch
// ---------------------------------------------------------------------------
extern "C" void kernel_launch(void* const* d_in, const int* in_sizes, int n_in,
                              void* d_out, int out_size) {
    const float* x    = (const float*)d_in[0];   // [B, C, L]
    const int*   idx  = (const int*)d_in[1];     // [B, L]
    // const float* W = d_in[2]; bias d_in[3] (bias cancels under InstanceNorm)
    const float* W    = (const float*)d_in[2];
    float* out = (float*)d_out;

    cudaFuncSetAttribute(gemm_kernel, cudaFuncAttributeMaxDynamicSharedMemorySize, GSMEM);

    prep_kernel<<<(TWOC * KTOT + 255) / 256, 256>>>(W);

    dim3 cgrid(LSQ / 32, CCH / 128, BATCH);
    conv_kernel<<<cgrid, 256>>>(x);

    dim3 ggrid(LSQ / 128, TWOC / 128, BATCH);
    gemm_kernel<<<ggrid, 256, GSMEM>>>();

    dim3 ngrid(CCH / 8, BATCH);
    norm_kernel<<<ngrid, 256>>>(idx, out);
}